// round 7
// baseline (speedup 1.0000x reference)
#include <cuda_runtime.h>
#include <cuda_bf16.h>
#include <cstddef>

// ---------------------------------------------------------------------------
// Problem constants
// ---------------------------------------------------------------------------
#define NB     2048     // batch
#define LX     168      // encoder steps
#define FF     64       // encoder features
#define HID    256      // hidden
#define LY     72       // decoder steps
#define FT     22       // future feats
#define FOUTV  10       // output size
#define DECIN  32       // FT + FOUTV
#define REGH   128
#define CLSH   128

#define BT     16       // batch rows per CTA
#define NCTA   (NB / BT)        // 128
#define NTHR   512      // 2 threads per hidden unit (row-half split)
#define RPAIR  8        // total row pairs per CTA
#define RPT    4        // row pairs per thread
#define HSTR   10       // float2 stride per k-row (80B: 16B-aligned, low conflicts)

// ---------------------------------------------------------------------------
// Packed weight scratch (device globals -- no allocation allowed)
//   W*rz[k][u] = (w_r(u,k), w_z(u,k)) ; W*n[k][u] = w_n(u,k)
// ---------------------------------------------------------------------------
__device__ float2 g_encWrz[HID * HID];
__device__ float  g_encWn [HID * HID];
__device__ float2 g_encIrz[FF * HID];
__device__ float  g_encIn [FF * HID];
__device__ float2 g_decWrz[HID * HID];
__device__ float  g_decWn [HID * HID];
__device__ float2 g_decIrz[DECIN * HID];
__device__ float  g_decIn [DECIN * HID];
__device__ float  g_hW0T[HID * 256];      // head layer0: units 0..127 temphr, 128..255 class
__device__ float  g_hb0 [256];
__device__ float  g_hW1 [FOUTV * REGH];   // rows 0..1 temphr, 2..9 class
__device__ float  g_hb1 [FOUTV];
__device__ float4 g_encB[HID];            // (bir+bhr, biz+bhz, bin, bhn)
__device__ float4 g_decB[HID];

// ---------------------------------------------------------------------------
// f32x2 packed-FMA helpers (sm_103a: fma.rn.f32x2)
// ---------------------------------------------------------------------------
typedef unsigned long long ull;

__device__ __forceinline__ ull fma2(ull a, ull b, ull c) {
    ull d;
    asm("fma.rn.f32x2 %0, %1, %2, %3;" : "=l"(d) : "l"(a), "l"(b), "l"(c));
    return d;
}
__device__ __forceinline__ ull bcast2(float x) {
    ull d; unsigned int xi = __float_as_uint(x);
    asm("mov.b64 %0, {%1, %2};" : "=l"(d) : "r"(xi), "r"(xi));
    return d;
}
__device__ __forceinline__ float2 unp2(ull v) {
    unsigned int lo, hi;
    asm("mov.b64 {%0, %1}, %2;" : "=r"(lo), "=r"(hi) : "l"(v));
    return make_float2(__uint_as_float(lo), __uint_as_float(hi));
}

__device__ __forceinline__ float sigf(float x) {
    return __fdividef(1.0f, 1.0f + __expf(-x));
}
__device__ __forceinline__ float tanhfast(float x) {
    return __fdividef(2.0f, 1.0f + __expf(-2.0f * x)) - 1.0f;
}
__device__ __forceinline__ float smelu(float x) {
    if (x >= 1.1f) return x;
    if (x <= -1.1f) return 0.0f;
    float u = x + 1.1f;
    return u * u * (1.0f / 4.4f);
}

// ---------------------------------------------------------------------------
// Setup kernel: transpose/pack weights into streaming-friendly layouts.
// ---------------------------------------------------------------------------
__global__ void setup_kernel(
    const float* __restrict__ encWih, const float* __restrict__ encWhh,
    const float* __restrict__ encBih, const float* __restrict__ encBhh,
    const float* __restrict__ decWih, const float* __restrict__ decWhh,
    const float* __restrict__ decBih, const float* __restrict__ decBhh,
    const float* __restrict__ thW0,  const float* __restrict__ thB0,
    const float* __restrict__ thW1,  const float* __restrict__ thB1,
    const float* __restrict__ clW0,  const float* __restrict__ clB0,
    const float* __restrict__ clW1,  const float* __restrict__ clB1)
{
    int id = blockIdx.x * blockDim.x + threadIdx.x;   // 0 .. 65535
    int u  = id & 255;
    int k  = id >> 8;                                  // 0 .. 255

    g_encWrz[k * HID + u] = make_float2(encWhh[u * HID + k], encWhh[(HID + u) * HID + k]);
    g_encWn [k * HID + u] = encWhh[(2 * HID + u) * HID + k];
    g_decWrz[k * HID + u] = make_float2(decWhh[u * HID + k], decWhh[(HID + u) * HID + k]);
    g_decWn [k * HID + u] = decWhh[(2 * HID + u) * HID + k];

    g_hW0T[k * 256 + u] = (u < REGH) ? thW0[u * HID + k] : clW0[(u - REGH) * HID + k];

    if (k < FF) {
        g_encIrz[k * HID + u] = make_float2(encWih[u * FF + k], encWih[(HID + u) * FF + k]);
        g_encIn [k * HID + u] = encWih[(2 * HID + u) * FF + k];
    }
    if (k < DECIN) {
        g_decIrz[k * HID + u] = make_float2(decWih[u * DECIN + k], decWih[(HID + u) * DECIN + k]);
        g_decIn [k * HID + u] = decWih[(2 * HID + u) * DECIN + k];
    }
    if (id < HID) {
        g_encB[id] = make_float4(encBih[id] + encBhh[id],
                                 encBih[HID + id] + encBhh[HID + id],
                                 encBih[2 * HID + id],
                                 encBhh[2 * HID + id]);
        g_decB[id] = make_float4(decBih[id] + decBhh[id],
                                 decBih[HID + id] + decBhh[HID + id],
                                 decBih[2 * HID + id],
                                 decBhh[2 * HID + id]);
        g_hb0[id] = (id < REGH) ? thB0[id] : clB0[id - REGH];
    }
    if (id < FOUTV * REGH) {
        int o = id >> 7, kk = id & 127;
        g_hW1[id] = (o < 2) ? thW1[o * REGH + kk] : clW1[(o - 2) * CLSH + kk];
    }
    if (id < FOUTV) g_hb1[id] = (id < 2) ? thB1[id] : clB1[id - 2];
}

// ---------------------------------------------------------------------------
// GEMM accumulate over K for this thread's unit u and its 4 row-pairs.
// src is pre-offset to this thread's row-pair half; 2x LDS.128 per k.
// ---------------------------------------------------------------------------
__device__ __forceinline__ void accum_rzn(
    const float2* __restrict__ Wrz, const float* __restrict__ Wn,
    const ull* __restrict__ src, int K, int u,
    ull aR[RPT], ull aZ[RPT], ull aN[RPT])
{
#pragma unroll 4
    for (int k = 0; k < K; k++) {
        float2 w2 = Wrz[k * HID + u];
        float  wn = Wn [k * HID + u];
        ull br = bcast2(w2.x), bz = bcast2(w2.y), bn = bcast2(wn);
        ulonglong2 p0 = *(const ulonglong2*)(src + k * HSTR);
        ulonglong2 p1 = *(const ulonglong2*)(src + k * HSTR + 2);
        aR[0] = fma2(p0.x, br, aR[0]);
        aZ[0] = fma2(p0.x, bz, aZ[0]);
        aN[0] = fma2(p0.x, bn, aN[0]);
        aR[1] = fma2(p0.y, br, aR[1]);
        aZ[1] = fma2(p0.y, bz, aZ[1]);
        aN[1] = fma2(p0.y, bn, aN[1]);
        aR[2] = fma2(p1.x, br, aR[2]);
        aZ[2] = fma2(p1.x, bz, aZ[2]);
        aN[2] = fma2(p1.x, bn, aN[2]);
        aR[3] = fma2(p1.y, br, aR[3]);
        aZ[3] = fma2(p1.y, bz, aZ[3]);
        aN[3] = fma2(p1.y, bn, aN[3]);
    }
}

// ---------------------------------------------------------------------------
// Persistent recurrent kernel: 1 CTA per 16 batch rows, 512 threads.
// Thread t: unit u = t&255, row-half hf = t>>8 (row pairs hf*4 .. hf*4+3).
// ---------------------------------------------------------------------------
__global__ void __launch_bounds__(NTHR, 1) rnn_kernel(
    const float* __restrict__ x_f,   // (N, LX, FF)
    const float* __restrict__ y_t,   // (N, LY+1, FT)
    const float* __restrict__ p,     // (N, LY+1, FOUTV)
    float* __restrict__ out)         // (N, LY, FOUTV)
{
    __shared__ float2 hs [HID * HSTR];   // hidden state, packed row-pairs
    __shared__ float2 us [FF  * HSTR];   // step input, packed row-pairs
    __shared__ float2 aps[256 * HSTR];   // head-0 activations, packed

    const int t       = threadIdx.x;
    const int u       = t & 255;         // hidden / head unit
    const int hf      = t >> 8;          // row-half: 0 or 1
    const int rpbase  = hf * RPT;        // first row pair for this thread
    const int rowbase = blockIdx.x * BT;

    float hreg[2 * RPT];                 // this thread's 8 rows of h (regs)
#pragma unroll
    for (int r = 0; r < 2 * RPT; r++) hreg[r] = 0.0f;
#pragma unroll
    for (int j = 0; j < RPT; j++) hs[u * HSTR + rpbase + j] = make_float2(0.0f, 0.0f);

    const ull* hsu = (const ull*)hs + rpbase;   // pre-offset to our half
    const ull* usu = (const ull*)us + rpbase;

    const float4 eb = g_encB[u];

    // ================= encoder =================
    for (int step = 0; step < LX; step++) {
        // load u tile: x_f[rowbase.., step, :] -> us[k][rp]; 512 threads cover 64*8
        {
            int k = t & (FF - 1), rp = t >> 6;
            size_t base = ((size_t)(rowbase + 2 * rp) * LX + step) * FF + k;
            us[k * HSTR + rp] = make_float2(x_f[base], x_f[base + (size_t)LX * FF]);
        }
        __syncthreads();   // us ready; hs (prev step) visible

        ull aR[RPT], aZ[RPT], aGN[RPT], aHN[RPT];
        {
            ull bR = bcast2(eb.x), bZ = bcast2(eb.y), bGN = bcast2(eb.z), bHN = bcast2(eb.w);
#pragma unroll
            for (int j = 0; j < RPT; j++) { aR[j] = bR; aZ[j] = bZ; aGN[j] = bGN; aHN[j] = bHN; }
        }
        accum_rzn(g_encWrz, g_encWn, hsu, HID, u, aR, aZ, aHN);   // hidden part (n -> aHN)
        accum_rzn(g_encIrz, g_encIn, usu, FF,  u, aR, aZ, aGN);   // input part  (n -> aGN)
        __syncthreads();   // all reads of hs/us done

        float nh[2 * RPT];
#pragma unroll
        for (int j = 0; j < RPT; j++) {
            float2 vR = unp2(aR[j]), vZ = unp2(aZ[j]), vGN = unp2(aGN[j]), vHN = unp2(aHN[j]);
            float r0 = sigf(vR.x), z0 = sigf(vZ.x), n0 = tanhfast(vGN.x + r0 * vHN.x);
            float r1 = sigf(vR.y), z1 = sigf(vZ.y), n1 = tanhfast(vGN.y + r1 * vHN.y);
            float h0 = n0 + z0 * (hreg[2 * j]     - n0);
            float h1 = n1 + z1 * (hreg[2 * j + 1] - n1);
            hreg[2 * j] = h0; hreg[2 * j + 1] = h1;
            nh[2 * j] = h0; nh[2 * j + 1] = h1;
        }
        // two 16B stores (aligned: u*80 + {0,32})
        *(float4*)(&hs[u * HSTR + rpbase])     = make_float4(nh[0], nh[1], nh[2], nh[3]);
        *(float4*)(&hs[u * HSTR + rpbase + 2]) = make_float4(nh[4], nh[5], nh[6], nh[7]);
        // next iteration's first __syncthreads orders these writes vs reads
    }

    // ================= decoder =================
    const float4 db = g_decB[u];
    const float  b0 = g_hb0[u];

    for (int i = 0; i < LY; i++) {
        const int j = (i == 0) ? 0 : (i - 1);
        // load dec input: concat(y_t[:, j, 0:22], p[:, j, 0:10]) -> 32 feats
        if (t < DECIN * RPAIR) {
            int k = t & (DECIN - 1), rp = t >> 5;
            int r0 = rowbase + 2 * rp;
            float a, b;
            if (k < FT) {
                size_t base = ((size_t)r0 * (LY + 1) + j) * FT + k;
                a = y_t[base]; b = y_t[base + (size_t)(LY + 1) * FT];
            } else {
                size_t base = ((size_t)r0 * (LY + 1) + j) * FOUTV + (k - FT);
                a = p[base]; b = p[base + (size_t)(LY + 1) * FOUTV];
            }
            us[k * HSTR + rp] = make_float2(a, b);
        }
        __syncthreads();

        ull aR[RPT], aZ[RPT], aGN[RPT], aHN[RPT];
        {
            ull bR = bcast2(db.x), bZ = bcast2(db.y), bGN = bcast2(db.z), bHN = bcast2(db.w);
#pragma unroll
            for (int jj = 0; jj < RPT; jj++) { aR[jj] = bR; aZ[jj] = bZ; aGN[jj] = bGN; aHN[jj] = bHN; }
        }
        accum_rzn(g_decWrz, g_decWn, hsu, HID,   u, aR, aZ, aHN);
        accum_rzn(g_decIrz, g_decIn, usu, DECIN, u, aR, aZ, aGN);
        __syncthreads();   // reads of hs done -> safe to overwrite

        float nh[2 * RPT];
#pragma unroll
        for (int jj = 0; jj < RPT; jj++) {
            float2 vR = unp2(aR[jj]), vZ = unp2(aZ[jj]), vGN = unp2(aGN[jj]), vHN = unp2(aHN[jj]);
            float r0 = sigf(vR.x), z0 = sigf(vZ.x), n0 = tanhfast(vGN.x + r0 * vHN.x);
            float r1 = sigf(vR.y), z1 = sigf(vZ.y), n1 = tanhfast(vGN.y + r1 * vHN.y);
            float h0 = n0 + z0 * (hreg[2 * jj]     - n0);
            float h1 = n1 + z1 * (hreg[2 * jj + 1] - n1);
            hreg[2 * jj] = h0; hreg[2 * jj + 1] = h1;
            nh[2 * jj] = h0; nh[2 * jj + 1] = h1;
        }
        *(float4*)(&hs[u * HSTR + rpbase])     = make_float4(nh[0], nh[1], nh[2], nh[3]);
        *(float4*)(&hs[u * HSTR + rpbase + 2]) = make_float4(nh[4], nh[5], nh[6], nh[7]);
        __syncthreads();   // new h visible for the head GEMM

        // ---- head layer 0: a = smelu(h2 @ W0^T + b0), 256 combined units ----
        ull aA[RPT];
        {
            ull b0p = bcast2(b0);
#pragma unroll
            for (int jj = 0; jj < RPT; jj++) aA[jj] = b0p;
        }
#pragma unroll 4
        for (int k = 0; k < HID; k++) {
            ull bw = bcast2(g_hW0T[k * 256 + u]);
            ulonglong2 p0 = *(const ulonglong2*)(hsu + k * HSTR);
            ulonglong2 p1 = *(const ulonglong2*)(hsu + k * HSTR + 2);
            aA[0] = fma2(p0.x, bw, aA[0]);
            aA[1] = fma2(p0.y, bw, aA[1]);
            aA[2] = fma2(p1.x, bw, aA[2]);
            aA[3] = fma2(p1.y, bw, aA[3]);
        }
#pragma unroll
        for (int jj = 0; jj < RPT; jj++) {
            float2 v = unp2(aA[jj]);
            aps[u * HSTR + rpbase + jj] = make_float2(smelu(v.x), smelu(v.y));
        }
        __syncthreads();   // aps ready

        // ---- head layer 1: 10 outputs x 16 rows = 160 dots of length 128 ----
        if (t < BT * FOUTV) {
            int row = t / FOUTV, o = t - row * FOUTV;
            int koff = (o < 2) ? 0 : REGH;
            const float* apf = (const float*)aps;   // flat: unit k -> k*2*HSTR + row
            const float* w   = &g_hW1[o * REGH];
            float s = g_hb1[o];
#pragma unroll 4
            for (int k = 0; k < REGH; k++)
                s += apf[(koff + k) * (2 * HSTR) + row] * w[k];
            out[((size_t)(rowbase + row) * LY + i) * FOUTV + o] = s;
        }
        // next iteration's first __syncthreads fences aps/us reuse
    }
}

// ---------------------------------------------------------------------------
// Launch. d_in order: x_f, x(unused), y_t, p, enc_Wih, enc_Whh, enc_bih,
// enc_bhh, dec_Wih, dec_Whh, dec_bih, dec_bhh, th_W0, th_b0, th_W1, th_b1,
// cl_W0, cl_b0, cl_W1, cl_b1
// ---------------------------------------------------------------------------
extern "C" void kernel_launch(void* const* d_in, const int* in_sizes, int n_in,
                              void* d_out, int out_size)
{
    const float* x_f    = (const float*)d_in[0];
    const float* y_t    = (const float*)d_in[2];
    const float* p      = (const float*)d_in[3];
    const float* encWih = (const float*)d_in[4];
    const float* encWhh = (const float*)d_in[5];
    const float* encBih = (const float*)d_in[6];
    const float* encBhh = (const float*)d_in[7];
    const float* decWih = (const float*)d_in[8];
    const float* decWhh = (const float*)d_in[9];
    const float* decBih = (const float*)d_in[10];
    const float* decBhh = (const float*)d_in[11];
    const float* thW0   = (const float*)d_in[12];
    const float* thB0   = (const float*)d_in[13];
    const float* thW1   = (const float*)d_in[14];
    const float* thB1   = (const float*)d_in[15];
    const float* clW0   = (const float*)d_in[16];
    const float* clB0   = (const float*)d_in[17];
    const float* clW1   = (const float*)d_in[18];
    const float* clB1   = (const float*)d_in[19];
    float* out = (float*)d_out;

    setup_kernel<<<256, 256>>>(encWih, encWhh, encBih, encBhh,
                               decWih, decWhh, decBih, decBhh,
                               thW0, thB0, thW1, thB1,
                               clW0, clB0, clW1, clB1);
    rnn_kernel<<<NCTA, NTHR>>>(x_f, y_t, p, out);
}

// round 12
// speedup vs baseline: 1.2136x; 1.2136x over previous
#include <cuda_runtime.h>
#include <cuda_bf16.h>
#include <cstddef>

// ---------------------------------------------------------------------------
// Problem constants
// ---------------------------------------------------------------------------
#define NB     2048     // batch
#define LX     168      // encoder steps
#define FF     64       // encoder features
#define HID    256      // hidden
#define LY     72       // decoder steps
#define FT     22       // future feats
#define FOUTV  10       // output size
#define DECIN  32       // FT + FOUTV
#define REGH   128
#define CLSH   128

#define BT     16       // batch rows per CTA
#define NCTA   (NB / BT)        // 128
#define NTHR   256
#define RPAIR  8        // row pairs per CTA (= per thread)
#define HSTR   10       // float2 stride per k-row (80B: 16B-aligned)
#define GRP    4        // weight prefetch group (kept small: register budget!)
#define KPAD   8        // pad rows so the one-group over-prefetch stays in bounds

// ---------------------------------------------------------------------------
// Packed weight scratch (device globals -- no allocation allowed).
// Weights stored PRE-DUPLICATED for fma.rn.f32x2:
//   W*rz2[k][u] = (wr,wr,wz,wz)  -> one LDG.128, both gate broadcasts ready
//   W*n2 [k][u] = (wn,wn)        -> one LDG.64
// This removes the 6 ALU MOVs/k that the scalar->pair broadcast cost.
// ---------------------------------------------------------------------------
__device__ float4 g_encWrz2[(HID + KPAD) * HID];
__device__ float2 g_encWn2 [(HID + KPAD) * HID];
__device__ float4 g_encIrz2[(FF + KPAD) * HID];
__device__ float2 g_encIn2 [(FF + KPAD) * HID];
__device__ float4 g_decWrz2[(HID + KPAD) * HID];
__device__ float2 g_decWn2 [(HID + KPAD) * HID];
__device__ float4 g_decIrz2[(DECIN + KPAD) * HID];
__device__ float2 g_decIn2 [(DECIN + KPAD) * HID];
__device__ float2 g_hW0D[(HID + KPAD) * 256]; // head L0 dup: 0..127 temphr, 128..255 class
__device__ float  g_hb0 [256];
__device__ float  g_hW1 [FOUTV * REGH];       // rows 0..1 temphr, 2..9 class
__device__ float  g_hb1 [FOUTV];
__device__ float4 g_encB[HID];                // (bir+bhr, biz+bhz, bin, bhn)
__device__ float4 g_decB[HID];

// ---------------------------------------------------------------------------
// f32x2 packed-FMA helpers (sm_103a: fma.rn.f32x2)
// ---------------------------------------------------------------------------
typedef unsigned long long ull;

__device__ __forceinline__ ull fma2(ull a, ull b, ull c) {
    ull d;
    asm("fma.rn.f32x2 %0, %1, %2, %3;" : "=l"(d) : "l"(a), "l"(b), "l"(c));
    return d;
}
__device__ __forceinline__ ull bcast2(float x) {
    ull d; unsigned int xi = __float_as_uint(x);
    asm("mov.b64 %0, {%1, %2};" : "=l"(d) : "r"(xi), "r"(xi));
    return d;
}
__device__ __forceinline__ float2 unp2(ull v) {
    unsigned int lo, hi;
    asm("mov.b64 {%0, %1}, %2;" : "=r"(lo), "=r"(hi) : "l"(v));
    return make_float2(__uint_as_float(lo), __uint_as_float(hi));
}

__device__ __forceinline__ float sigf(float x) {
    return __fdividef(1.0f, 1.0f + __expf(-x));
}
__device__ __forceinline__ float tanhfast(float x) {
    return __fdividef(2.0f, 1.0f + __expf(-2.0f * x)) - 1.0f;
}
__device__ __forceinline__ float smelu(float x) {
    if (x >= 1.1f) return x;
    if (x <= -1.1f) return 0.0f;
    float u = x + 1.1f;
    return u * u * (1.0f / 4.4f);
}

// ---------------------------------------------------------------------------
// Setup kernel: transpose/pack weights (duplicated layout).
// ---------------------------------------------------------------------------
__global__ void setup_kernel(
    const float* __restrict__ encWih, const float* __restrict__ encWhh,
    const float* __restrict__ encBih, const float* __restrict__ encBhh,
    const float* __restrict__ decWih, const float* __restrict__ decWhh,
    const float* __restrict__ decBih, const float* __restrict__ decBhh,
    const float* __restrict__ thW0,  const float* __restrict__ thB0,
    const float* __restrict__ thW1,  const float* __restrict__ thB1,
    const float* __restrict__ clW0,  const float* __restrict__ clB0,
    const float* __restrict__ clW1,  const float* __restrict__ clB1)
{
    int id = blockIdx.x * blockDim.x + threadIdx.x;   // 0 .. 65535
    int u  = id & 255;
    int k  = id >> 8;                                  // 0 .. 255

    {
        float wr = encWhh[u * HID + k];
        float wz = encWhh[(HID + u) * HID + k];
        float wn = encWhh[(2 * HID + u) * HID + k];
        g_encWrz2[k * HID + u] = make_float4(wr, wr, wz, wz);
        g_encWn2 [k * HID + u] = make_float2(wn, wn);
    }
    {
        float wr = decWhh[u * HID + k];
        float wz = decWhh[(HID + u) * HID + k];
        float wn = decWhh[(2 * HID + u) * HID + k];
        g_decWrz2[k * HID + u] = make_float4(wr, wr, wz, wz);
        g_decWn2 [k * HID + u] = make_float2(wn, wn);
    }
    {
        float w = (u < REGH) ? thW0[u * HID + k] : clW0[(u - REGH) * HID + k];
        g_hW0D[k * 256 + u] = make_float2(w, w);
    }
    if (k < FF) {
        float wr = encWih[u * FF + k];
        float wz = encWih[(HID + u) * FF + k];
        float wn = encWih[(2 * HID + u) * FF + k];
        g_encIrz2[k * HID + u] = make_float4(wr, wr, wz, wz);
        g_encIn2 [k * HID + u] = make_float2(wn, wn);
    }
    if (k < DECIN) {
        float wr = decWih[u * DECIN + k];
        float wz = decWih[(HID + u) * DECIN + k];
        float wn = decWih[(2 * HID + u) * DECIN + k];
        g_decIrz2[k * HID + u] = make_float4(wr, wr, wz, wz);
        g_decIn2 [k * HID + u] = make_float2(wn, wn);
    }
    if (id < HID) {
        g_encB[id] = make_float4(encBih[id] + encBhh[id],
                                 encBih[HID + id] + encBhh[HID + id],
                                 encBih[2 * HID + id],
                                 encBhh[2 * HID + id]);
        g_decB[id] = make_float4(decBih[id] + decBhh[id],
                                 decBih[HID + id] + decBhh[HID + id],
                                 decBih[2 * HID + id],
                                 decBhh[2 * HID + id]);
        g_hb0[id] = (id < REGH) ? thB0[id] : clB0[id - REGH];
    }
    if (id < FOUTV * REGH) {
        int o = id >> 7, kk = id & 127;
        g_hW1[id] = (o < 2) ? thW1[o * REGH + kk] : clW1[(o - 2) * CLSH + kk];
    }
    if (id < FOUTV) g_hb1[id] = (id < 2) ? thB1[id] : clB1[id - 2];
}

// ---------------------------------------------------------------------------
// Software-pipelined GEMM pieces (GRP=4, duplicated weights).
// ---------------------------------------------------------------------------
__device__ __forceinline__ void load_grpW(
    const float4* __restrict__ Wrz2, const float2* __restrict__ Wn2,
    int u, int k0, ulonglong2 wrz[GRP], ull wn[GRP])
{
#pragma unroll
    for (int j = 0; j < GRP; j++) {
        wrz[j] = *(const ulonglong2*)(Wrz2 + (k0 + j) * HID + u);
        wn [j] = *(const ull*)      (Wn2  + (k0 + j) * HID + u);
    }
}

__device__ __forceinline__ void consume_grpW(
    const ulonglong2 wrz[GRP], const ull wn[GRP],
    const ull* __restrict__ src, int k0,
    ull aR[RPAIR], ull aZ[RPAIR], ull aN[RPAIR])
{
#pragma unroll
    for (int j = 0; j < GRP; j++) {
        ull br = wrz[j].x, bz = wrz[j].y, bn = wn[j];
        const ull* s = src + (k0 + j) * HSTR;
        ulonglong2 p0 = *(const ulonglong2*)(s + 0);
        ulonglong2 p1 = *(const ulonglong2*)(s + 2);
        ulonglong2 p2 = *(const ulonglong2*)(s + 4);
        ulonglong2 p3 = *(const ulonglong2*)(s + 6);
        aR[0] = fma2(p0.x, br, aR[0]); aZ[0] = fma2(p0.x, bz, aZ[0]); aN[0] = fma2(p0.x, bn, aN[0]);
        aR[1] = fma2(p0.y, br, aR[1]); aZ[1] = fma2(p0.y, bz, aZ[1]); aN[1] = fma2(p0.y, bn, aN[1]);
        aR[2] = fma2(p1.x, br, aR[2]); aZ[2] = fma2(p1.x, bz, aZ[2]); aN[2] = fma2(p1.x, bn, aN[2]);
        aR[3] = fma2(p1.y, br, aR[3]); aZ[3] = fma2(p1.y, bz, aZ[3]); aN[3] = fma2(p1.y, bn, aN[3]);
        aR[4] = fma2(p2.x, br, aR[4]); aZ[4] = fma2(p2.x, bz, aZ[4]); aN[4] = fma2(p2.x, bn, aN[4]);
        aR[5] = fma2(p2.y, br, aR[5]); aZ[5] = fma2(p2.y, bz, aZ[5]); aN[5] = fma2(p2.y, bn, aN[5]);
        aR[6] = fma2(p3.x, br, aR[6]); aZ[6] = fma2(p3.x, bz, aZ[6]); aN[6] = fma2(p3.x, bn, aN[6]);
        aR[7] = fma2(p3.y, br, aR[7]); aZ[7] = fma2(p3.y, bz, aZ[7]); aN[7] = fma2(p3.y, bn, aN[7]);
    }
}

// Ping-pong pipelined accumulate over K rows (K multiple of 2*GRP).
// Over-prefetches one group past K (pad rows: loaded, never consumed).
__device__ __forceinline__ void accum_pf(
    const float4* __restrict__ Wrz2, const float2* __restrict__ Wn2,
    const ull* __restrict__ src, int K, int u,
    ull aR[RPAIR], ull aZ[RPAIR], ull aN[RPAIR])
{
    ulonglong2 wA[GRP], wB[GRP];
    ull        nA[GRP], nB[GRP];
    load_grpW(Wrz2, Wn2, u, 0, wA, nA);
    for (int k0 = 0; k0 < K; k0 += 2 * GRP) {
        load_grpW(Wrz2, Wn2, u, k0 + GRP, wB, nB);
        consume_grpW(wA, nA, src, k0, aR, aZ, aN);
        load_grpW(Wrz2, Wn2, u, k0 + 2 * GRP, wA, nA);   // pad-covered over-read
        consume_grpW(wB, nB, src, k0 + GRP, aR, aZ, aN);
    }
}

// Head layer-0 variants (one duplicated weight per k).
__device__ __forceinline__ void load_grpH(
    const float2* __restrict__ W, int u, int k0, ull w[GRP])
{
#pragma unroll
    for (int j = 0; j < GRP; j++) w[j] = *(const ull*)(W + (k0 + j) * 256 + u);
}
__device__ __forceinline__ void consume_grpH(
    const ull w[GRP], const ull* __restrict__ src, int k0, ull aA[RPAIR])
{
#pragma unroll
    for (int j = 0; j < GRP; j++) {
        ull bw = w[j];
        const ull* s = src + (k0 + j) * HSTR;
        ulonglong2 p0 = *(const ulonglong2*)(s + 0);
        ulonglong2 p1 = *(const ulonglong2*)(s + 2);
        ulonglong2 p2 = *(const ulonglong2*)(s + 4);
        ulonglong2 p3 = *(const ulonglong2*)(s + 6);
        aA[0] = fma2(p0.x, bw, aA[0]); aA[1] = fma2(p0.y, bw, aA[1]);
        aA[2] = fma2(p1.x, bw, aA[2]); aA[3] = fma2(p1.y, bw, aA[3]);
        aA[4] = fma2(p2.x, bw, aA[4]); aA[5] = fma2(p2.y, bw, aA[5]);
        aA[6] = fma2(p3.x, bw, aA[6]); aA[7] = fma2(p3.y, bw, aA[7]);
    }
}

// ---------------------------------------------------------------------------
// Persistent recurrent kernel: one CTA per 16 batch rows, full time loop.
// Thread t owns hidden/head unit t and all 8 row-pairs.
// ---------------------------------------------------------------------------
__global__ void __launch_bounds__(NTHR, 1) rnn_kernel(
    const float* __restrict__ x_f,   // (N, LX, FF)
    const float* __restrict__ y_t,   // (N, LY+1, FT)
    const float* __restrict__ p,     // (N, LY+1, FOUTV)
    float* __restrict__ out)         // (N, LY, FOUTV)
{
    __shared__ float2 hs [HID * HSTR];   // hidden state, packed row-pairs
    __shared__ float2 us [FF  * HSTR];   // step input, packed row-pairs
    __shared__ float2 aps[256 * HSTR];   // head-0 activations, packed

    const int t       = threadIdx.x;     // unit index
    const int rowbase = blockIdx.x * BT;

    float hreg[BT];
#pragma unroll
    for (int r = 0; r < BT; r++) hreg[r] = 0.0f;
#pragma unroll
    for (int rp = 0; rp < RPAIR; rp++) hs[t * HSTR + rp] = make_float2(0.0f, 0.0f);

    const ull* hsu = (const ull*)hs;
    const ull* usu = (const ull*)us;

    const float4 eb = g_encB[t];

    // ================= encoder =================
    for (int step = 0; step < LX; step++) {
        // load u tile: x_f[rowbase.., step, :] packed into us[k][rp]
        for (int idx = t; idx < FF * RPAIR; idx += NTHR) {
            int k = idx & (FF - 1), rp = idx >> 6;
            size_t base = ((size_t)(rowbase + 2 * rp) * LX + step) * FF + k;
            us[k * HSTR + rp] = make_float2(x_f[base], x_f[base + (size_t)LX * FF]);
        }
        __syncthreads();   // us ready; hs (prev step) visible

        ull aR[RPAIR], aZ[RPAIR], aGN[RPAIR], aHN[RPAIR];
        {
            ull bR = bcast2(eb.x), bZ = bcast2(eb.y), bGN = bcast2(eb.z), bHN = bcast2(eb.w);
#pragma unroll
            for (int rp = 0; rp < RPAIR; rp++) { aR[rp] = bR; aZ[rp] = bZ; aGN[rp] = bGN; aHN[rp] = bHN; }
        }
        accum_pf(g_encWrz2, g_encWn2, hsu, HID, t, aR, aZ, aHN);   // hidden part (n -> aHN)
        accum_pf(g_encIrz2, g_encIn2, usu, FF,  t, aR, aZ, aGN);   // input part  (n -> aGN)
        __syncthreads();   // all reads of hs/us done

        float nh[BT];
#pragma unroll
        for (int rp = 0; rp < RPAIR; rp++) {
            float2 vR = unp2(aR[rp]), vZ = unp2(aZ[rp]), vGN = unp2(aGN[rp]), vHN = unp2(aHN[rp]);
            float r0 = sigf(vR.x), z0 = sigf(vZ.x), n0 = tanhfast(vGN.x + r0 * vHN.x);
            float r1 = sigf(vR.y), z1 = sigf(vZ.y), n1 = tanhfast(vGN.y + r1 * vHN.y);
            float h0 = n0 + z0 * (hreg[2 * rp]     - n0);
            float h1 = n1 + z1 * (hreg[2 * rp + 1] - n1);
            hreg[2 * rp] = h0; hreg[2 * rp + 1] = h1;
            nh[2 * rp] = h0; nh[2 * rp + 1] = h1;
        }
        // four 16B aligned stores (row base t*80)
        *(float4*)(&hs[t * HSTR + 0]) = make_float4(nh[0],  nh[1],  nh[2],  nh[3]);
        *(float4*)(&hs[t * HSTR + 2]) = make_float4(nh[4],  nh[5],  nh[6],  nh[7]);
        *(float4*)(&hs[t * HSTR + 4]) = make_float4(nh[8],  nh[9],  nh[10], nh[11]);
        *(float4*)(&hs[t * HSTR + 6]) = make_float4(nh[12], nh[13], nh[14], nh[15]);
        // next iteration's first __syncthreads orders these writes vs reads
    }

    // ================= decoder =================
    const float4 db = g_decB[t];
    const float  b0 = g_hb0[t];

    for (int i = 0; i < LY; i++) {
        const int j = (i == 0) ? 0 : (i - 1);
        // load dec input: concat(y_t[:, j, 0:22], p[:, j, 0:10]) -> 32 feats
        {
            int k = t & (DECIN - 1), rp = t >> 5;     // 256 threads == DECIN*RPAIR
            int r0 = rowbase + 2 * rp;
            float a, b;
            if (k < FT) {
                size_t base = ((size_t)r0 * (LY + 1) + j) * FT + k;
                a = y_t[base]; b = y_t[base + (size_t)(LY + 1) * FT];
            } else {
                size_t base = ((size_t)r0 * (LY + 1) + j) * FOUTV + (k - FT);
                a = p[base]; b = p[base + (size_t)(LY + 1) * FOUTV];
            }
            us[k * HSTR + rp] = make_float2(a, b);
        }
        __syncthreads();

        ull aR[RPAIR], aZ[RPAIR], aGN[RPAIR], aHN[RPAIR];
        {
            ull bR = bcast2(db.x), bZ = bcast2(db.y), bGN = bcast2(db.z), bHN = bcast2(db.w);
#pragma unroll
            for (int rp = 0; rp < RPAIR; rp++) { aR[rp] = bR; aZ[rp] = bZ; aGN[rp] = bGN; aHN[rp] = bHN; }
        }
        accum_pf(g_decWrz2, g_decWn2, hsu, HID,   t, aR, aZ, aHN);
        accum_pf(g_decIrz2, g_decIn2, usu, DECIN, t, aR, aZ, aGN);
        __syncthreads();   // reads of hs done -> safe to overwrite

        float nh[BT];
#pragma unroll
        for (int rp = 0; rp < RPAIR; rp++) {
            float2 vR = unp2(aR[rp]), vZ = unp2(aZ[rp]), vGN = unp2(aGN[rp]), vHN = unp2(aHN[rp]);
            float r0 = sigf(vR.x), z0 = sigf(vZ.x), n0 = tanhfast(vGN.x + r0 * vHN.x);
            float r1 = sigf(vR.y), z1 = sigf(vZ.y), n1 = tanhfast(vGN.y + r1 * vHN.y);
            float h0 = n0 + z0 * (hreg[2 * rp]     - n0);
            float h1 = n1 + z1 * (hreg[2 * rp + 1] - n1);
            hreg[2 * rp] = h0; hreg[2 * rp + 1] = h1;
            nh[2 * rp] = h0; nh[2 * rp + 1] = h1;
        }
        *(float4*)(&hs[t * HSTR + 0]) = make_float4(nh[0],  nh[1],  nh[2],  nh[3]);
        *(float4*)(&hs[t * HSTR + 2]) = make_float4(nh[4],  nh[5],  nh[6],  nh[7]);
        *(float4*)(&hs[t * HSTR + 4]) = make_float4(nh[8],  nh[9],  nh[10], nh[11]);
        *(float4*)(&hs[t * HSTR + 6]) = make_float4(nh[12], nh[13], nh[14], nh[15]);
        __syncthreads();   // new h visible for the head GEMM

        // ---- head layer 0: a = smelu(h2 @ W0^T + b0), 256 combined units ----
        ull aA[RPAIR];
        {
            ull b0p = bcast2(b0);
#pragma unroll
            for (int rp = 0; rp < RPAIR; rp++) aA[rp] = b0p;
        }
        {
            ull wA[GRP], wB[GRP];
            load_grpH(g_hW0D, t, 0, wA);
            for (int k0 = 0; k0 < HID; k0 += 2 * GRP) {
                load_grpH(g_hW0D, t, k0 + GRP, wB);
                consume_grpH(wA, hsu, k0, aA);
                load_grpH(g_hW0D, t, k0 + 2 * GRP, wA);  // pad-covered over-read
                consume_grpH(wB, hsu, k0 + GRP, aA);
            }
        }
#pragma unroll
        for (int rp = 0; rp < RPAIR; rp++) {
            float2 v = unp2(aA[rp]);
            aps[t * HSTR + rp] = make_float2(smelu(v.x), smelu(v.y));
        }
        __syncthreads();   // aps ready

        // ---- head layer 1: 10 outputs x 16 rows = 160 dots of length 128 ----
        if (t < BT * FOUTV) {
            int row = t / FOUTV, o = t - row * FOUTV;
            int koff = (o < 2) ? 0 : REGH;
            const float* apf = (const float*)aps;   // flat: unit k -> k*2*HSTR + row
            const float* w   = &g_hW1[o * REGH];
            float s = g_hb1[o];
#pragma unroll 8
            for (int k = 0; k < REGH; k++)
                s += apf[(koff + k) * (2 * HSTR) + row] * w[k];
            out[((size_t)(rowbase + row) * LY + i) * FOUTV + o] = s;
        }
        // next iteration's first __syncthreads fences aps/us reuse
    }
}

// ---------------------------------------------------------------------------
// Launch. d_in order: x_f, x(unused), y_t, p, enc_Wih, enc_Whh, enc_bih,
// enc_bhh, dec_Wih, dec_Whh, dec_bih, dec_bhh, th_W0, th_b0, th_W1, th_b1,
// cl_W0, cl_b0, cl_W1, cl_b1
// ---------------------------------------------------------------------------
extern "C" void kernel_launch(void* const* d_in, const int* in_sizes, int n_in,
                              void* d_out, int out_size)
{
    const float* x_f    = (const float*)d_in[0];
    const float* y_t    = (const float*)d_in[2];
    const float* p      = (const float*)d_in[3];
    const float* encWih = (const float*)d_in[4];
    const float* encWhh = (const float*)d_in[5];
    const float* encBih = (const float*)d_in[6];
    const float* encBhh = (const float*)d_in[7];
    const float* decWih = (const float*)d_in[8];
    const float* decWhh = (const float*)d_in[9];
    const float* decBih = (const float*)d_in[10];
    const float* decBhh = (const float*)d_in[11];
    const float* thW0   = (const float*)d_in[12];
    const float* thB0   = (const float*)d_in[13];
    const float* thW1   = (const float*)d_in[14];
    const float* thB1   = (const float*)d_in[15];
    const float* clW0   = (const float*)d_in[16];
    const float* clB0   = (const float*)d_in[17];
    const float* clW1   = (const float*)d_in[18];
    const float* clB1   = (const float*)d_in[19];
    float* out = (float*)d_out;

    setup_kernel<<<256, 256>>>(encWih, encWhh, encBih, encBhh,
                               decWih, decWhh, decBih, decBhh,
                               thW0, thB0, thW1, thB1,
                               clW0, clB0, clW1, clB1);
    rnn_kernel<<<NCTA, NTHR>>>(x_f, y_t, p, out);
}

// round 13
// speedup vs baseline: 1.3673x; 1.1266x over previous
#include <cuda_runtime.h>
#include <cuda_bf16.h>
#include <cstddef>

// ---------------------------------------------------------------------------
// Problem constants
// ---------------------------------------------------------------------------
#define NB     2048     // batch
#define LX     168      // encoder steps
#define FF     64       // encoder features
#define HID    256      // hidden
#define LY     72      // decoder steps
#define FT     22       // future feats
#define FOUTV  10       // output size
#define DECIN  32       // FT + FOUTV
#define REGH   128
#define CLSH   128

#define BT     16       // batch rows per CTA
#define NCTA   (NB / BT)        // 128
#define NTHR   256
#define RPAIR  8        // row pairs per CTA (= per thread)
#define HSTR   10       // float2 stride per k-row (80B: 16B-aligned)
#define GRP    4        // weight prefetch group
#define KPAD   8        // pad rows: distance-2 pipeline over-reads rows K..K+7

// ---------------------------------------------------------------------------
// Packed weight scratch (device globals -- no allocation allowed).
// DE-DUPLICATED layout (halves L2 weight stream vs R12):
//   W*rz[k][u] = (wr, wz)  -> one LDG.64
//   W*n [k][u] = wn        -> one LDG.32
// Duplication into fma2 operands happens at consume via 1 MOV each (alu slack).
// ---------------------------------------------------------------------------
__device__ float2 g_encWrz[(HID + KPAD) * HID];
__device__ float  g_encWn [(HID + KPAD) * HID];
__device__ float2 g_encIrz[(FF + KPAD) * HID];
__device__ float  g_encIn [(FF + KPAD) * HID];
__device__ float2 g_decWrz[(HID + KPAD) * HID];
__device__ float  g_decWn [(HID + KPAD) * HID];
__device__ float2 g_decIrz[(DECIN + KPAD) * HID];
__device__ float  g_decIn [(DECIN + KPAD) * HID];
__device__ float  g_hW0T[(HID + KPAD) * 256]; // head L0: 0..127 temphr, 128..255 class
__device__ float  g_hb0 [256];
__device__ float  g_hW1 [FOUTV * REGH];       // rows 0..1 temphr, 2..9 class
__device__ float  g_hb1 [FOUTV];
__device__ float4 g_encB[HID];                // (bir+bhr, biz+bhz, bin, bhn)
__device__ float4 g_decB[HID];

// ---------------------------------------------------------------------------
// f32x2 packed-FMA helpers (sm_103a: fma.rn.f32x2)
// ---------------------------------------------------------------------------
typedef unsigned long long ull;

__device__ __forceinline__ ull fma2(ull a, ull b, ull c) {
    ull d;
    asm("fma.rn.f32x2 %0, %1, %2, %3;" : "=l"(d) : "l"(a), "l"(b), "l"(c));
    return d;
}
__device__ __forceinline__ ull bcast2(float x) {
    ull d; unsigned int xi = __float_as_uint(x);
    asm("mov.b64 %0, {%1, %2};" : "=l"(d) : "r"(xi), "r"(xi));
    return d;
}
__device__ __forceinline__ float2 unp2(ull v) {
    unsigned int lo, hi;
    asm("mov.b64 {%0, %1}, %2;" : "=r"(lo), "=r"(hi) : "l"(v));
    return make_float2(__uint_as_float(lo), __uint_as_float(hi));
}

__device__ __forceinline__ float sigf(float x) {
    return __fdividef(1.0f, 1.0f + __expf(-x));
}
__device__ __forceinline__ float tanhfast(float x) {
    return __fdividef(2.0f, 1.0f + __expf(-2.0f * x)) - 1.0f;
}
__device__ __forceinline__ float smelu(float x) {
    if (x >= 1.1f) return x;
    if (x <= -1.1f) return 0.0f;
    float u = x + 1.1f;
    return u * u * (1.0f / 4.4f);
}

// ---------------------------------------------------------------------------
// Setup kernel: transpose/pack weights into streaming-friendly layouts.
// ---------------------------------------------------------------------------
__global__ void setup_kernel(
    const float* __restrict__ encWih, const float* __restrict__ encWhh,
    const float* __restrict__ encBih, const float* __restrict__ encBhh,
    const float* __restrict__ decWih, const float* __restrict__ decWhh,
    const float* __restrict__ decBih, const float* __restrict__ decBhh,
    const float* __restrict__ thW0,  const float* __restrict__ thB0,
    const float* __restrict__ thW1,  const float* __restrict__ thB1,
    const float* __restrict__ clW0,  const float* __restrict__ clB0,
    const float* __restrict__ clW1,  const float* __restrict__ clB1)
{
    int id = blockIdx.x * blockDim.x + threadIdx.x;   // 0 .. 65535
    int u  = id & 255;
    int k  = id >> 8;                                  // 0 .. 255

    g_encWrz[k * HID + u] = make_float2(encWhh[u * HID + k], encWhh[(HID + u) * HID + k]);
    g_encWn [k * HID + u] = encWhh[(2 * HID + u) * HID + k];
    g_decWrz[k * HID + u] = make_float2(decWhh[u * HID + k], decWhh[(HID + u) * HID + k]);
    g_decWn [k * HID + u] = decWhh[(2 * HID + u) * HID + k];

    g_hW0T[k * 256 + u] = (u < REGH) ? thW0[u * HID + k] : clW0[(u - REGH) * HID + k];

    if (k < FF) {
        g_encIrz[k * HID + u] = make_float2(encWih[u * FF + k], encWih[(HID + u) * FF + k]);
        g_encIn [k * HID + u] = encWih[(2 * HID + u) * FF + k];
    }
    if (k < DECIN) {
        g_decIrz[k * HID + u] = make_float2(decWih[u * DECIN + k], decWih[(HID + u) * DECIN + k]);
        g_decIn [k * HID + u] = decWih[(2 * HID + u) * DECIN + k];
    }
    if (id < HID) {
        g_encB[id] = make_float4(encBih[id] + encBhh[id],
                                 encBih[HID + id] + encBhh[HID + id],
                                 encBih[2 * HID + id],
                                 encBhh[2 * HID + id]);
        g_decB[id] = make_float4(decBih[id] + decBhh[id],
                                 decBih[HID + id] + decBhh[HID + id],
                                 decBih[2 * HID + id],
                                 decBhh[2 * HID + id]);
        g_hb0[id] = (id < REGH) ? thB0[id] : clB0[id - REGH];
    }
    if (id < FOUTV * REGH) {
        int o = id >> 7, kk = id & 127;
        g_hW1[id] = (o < 2) ? thW1[o * REGH + kk] : clW1[(o - 2) * CLSH + kk];
    }
    if (id < FOUTV) g_hb1[id] = (id < 2) ? thB1[id] : clB1[id - 2];
}

// ---------------------------------------------------------------------------
// Software-pipelined GEMM pieces (GRP=4, de-duplicated weights, distance-2).
// ---------------------------------------------------------------------------
__device__ __forceinline__ void load_grpW(
    const float2* __restrict__ Wrz, const float* __restrict__ Wn,
    int u, int k0, float2 wrz[GRP], float wn[GRP])
{
#pragma unroll
    for (int j = 0; j < GRP; j++) {
        wrz[j] = Wrz[(k0 + j) * HID + u];
        wn [j] = Wn [(k0 + j) * HID + u];
    }
}

__device__ __forceinline__ void consume_grpW(
    const float2 wrz[GRP], const float wn[GRP],
    const ull* __restrict__ src, int k0,
    ull aR[RPAIR], ull aZ[RPAIR], ull aN[RPAIR])
{
#pragma unroll
    for (int j = 0; j < GRP; j++) {
        ull br = bcast2(wrz[j].x), bz = bcast2(wrz[j].y), bn = bcast2(wn[j]);
        const ull* s = src + (k0 + j) * HSTR;
        ulonglong2 p0 = *(const ulonglong2*)(s + 0);
        ulonglong2 p1 = *(const ulonglong2*)(s + 2);
        ulonglong2 p2 = *(const ulonglong2*)(s + 4);
        ulonglong2 p3 = *(const ulonglong2*)(s + 6);
        aR[0] = fma2(p0.x, br, aR[0]); aZ[0] = fma2(p0.x, bz, aZ[0]); aN[0] = fma2(p0.x, bn, aN[0]);
        aR[1] = fma2(p0.y, br, aR[1]); aZ[1] = fma2(p0.y, bz, aZ[1]); aN[1] = fma2(p0.y, bn, aN[1]);
        aR[2] = fma2(p1.x, br, aR[2]); aZ[2] = fma2(p1.x, bz, aZ[2]); aN[2] = fma2(p1.x, bn, aN[2]);
        aR[3] = fma2(p1.y, br, aR[3]); aZ[3] = fma2(p1.y, bz, aZ[3]); aN[3] = fma2(p1.y, bn, aN[3]);
        aR[4] = fma2(p2.x, br, aR[4]); aZ[4] = fma2(p2.x, bz, aZ[4]); aN[4] = fma2(p2.x, bn, aN[4]);
        aR[5] = fma2(p2.y, br, aR[5]); aZ[5] = fma2(p2.y, bz, aZ[5]); aN[5] = fma2(p2.y, bn, aN[5]);
        aR[6] = fma2(p3.x, br, aR[6]); aZ[6] = fma2(p3.x, bz, aZ[6]); aN[6] = fma2(p3.x, bn, aN[6]);
        aR[7] = fma2(p3.y, br, aR[7]); aZ[7] = fma2(p3.y, bz, aZ[7]); aN[7] = fma2(p3.y, bn, aN[7]);
    }
}

// Distance-2 pipelined accumulate over K rows (K multiple of 4*GRP: 256/64/32 ok).
// Loads run two groups ahead of consumption; the tail over-reads rows K..K+2*GRP-1,
// covered by KPAD padding (loaded, never consumed).
__device__ __forceinline__ void accum_pf(
    const float2* __restrict__ Wrz, const float* __restrict__ Wn,
    const ull* __restrict__ src, int K, int u,
    ull aR[RPAIR], ull aZ[RPAIR], ull aN[RPAIR])
{
    float2 wA[GRP], wB[GRP], wC[GRP], wD[GRP];
    float  nA[GRP], nB[GRP], nC[GRP], nD[GRP];
    load_grpW(Wrz, Wn, u, 0,   wA, nA);
    load_grpW(Wrz, Wn, u, GRP, wB, nB);
    for (int k0 = 0; k0 < K; k0 += 4 * GRP) {
        load_grpW(Wrz, Wn, u, k0 + 2 * GRP, wC, nC);
        load_grpW(Wrz, Wn, u, k0 + 3 * GRP, wD, nD);
        consume_grpW(wA, nA, src, k0,       aR, aZ, aN);
        consume_grpW(wB, nB, src, k0 + GRP, aR, aZ, aN);
        load_grpW(Wrz, Wn, u, k0 + 4 * GRP, wA, nA);   // pad-covered on last iter
        load_grpW(Wrz, Wn, u, k0 + 5 * GRP, wB, nB);   // pad-covered on last iter
        consume_grpW(wC, nC, src, k0 + 2 * GRP, aR, aZ, aN);
        consume_grpW(wD, nD, src, k0 + 3 * GRP, aR, aZ, aN);
    }
}

// Head layer-0 variants (one scalar weight per k).
__device__ __forceinline__ void load_grpH(
    const float* __restrict__ W, int u, int k0, float w[GRP])
{
#pragma unroll
    for (int j = 0; j < GRP; j++) w[j] = W[(k0 + j) * 256 + u];
}
__device__ __forceinline__ void consume_grpH(
    const float w[GRP], const ull* __restrict__ src, int k0, ull aA[RPAIR])
{
#pragma unroll
    for (int j = 0; j < GRP; j++) {
        ull bw = bcast2(w[j]);
        const ull* s = src + (k0 + j) * HSTR;
        ulonglong2 p0 = *(const ulonglong2*)(s + 0);
        ulonglong2 p1 = *(const ulonglong2*)(s + 2);
        ulonglong2 p2 = *(const ulonglong2*)(s + 4);
        ulonglong2 p3 = *(const ulonglong2*)(s + 6);
        aA[0] = fma2(p0.x, bw, aA[0]); aA[1] = fma2(p0.y, bw, aA[1]);
        aA[2] = fma2(p1.x, bw, aA[2]); aA[3] = fma2(p1.y, bw, aA[3]);
        aA[4] = fma2(p2.x, bw, aA[4]); aA[5] = fma2(p2.y, bw, aA[5]);
        aA[6] = fma2(p3.x, bw, aA[6]); aA[7] = fma2(p3.y, bw, aA[7]);
    }
}

// ---------------------------------------------------------------------------
// Persistent recurrent kernel: one CTA per 16 batch rows, full time loop.
// Thread t owns hidden/head unit t and all 8 row-pairs.
// ---------------------------------------------------------------------------
__global__ void __launch_bounds__(NTHR, 1) rnn_kernel(
    const float* __restrict__ x_f,   // (N, LX, FF)
    const float* __restrict__ y_t,   // (N, LY+1, FT)
    const float* __restrict__ p,     // (N, LY+1, FOUTV)
    float* __restrict__ out)         // (N, LY, FOUTV)
{
    __shared__ float2 hs [HID * HSTR];   // hidden state, packed row-pairs
    __shared__ float2 us [FF  * HSTR];   // step input, packed row-pairs
    __shared__ float2 aps[256 * HSTR];   // head-0 activations, packed

    const int t       = threadIdx.x;     // unit index
    const int rowbase = blockIdx.x * BT;

    float hreg[BT];
#pragma unroll
    for (int r = 0; r < BT; r++) hreg[r] = 0.0f;
#pragma unroll
    for (int rp = 0; rp < RPAIR; rp++) hs[t * HSTR + rp] = make_float2(0.0f, 0.0f);

    const ull* hsu = (const ull*)hs;
    const ull* usu = (const ull*)us;

    const float4 eb = g_encB[t];

    // ================= encoder =================
    for (int step = 0; step < LX; step++) {
        // load u tile: x_f[rowbase.., step, :] packed into us[k][rp]
        for (int idx = t; idx < FF * RPAIR; idx += NTHR) {
            int k = idx & (FF - 1), rp = idx >> 6;
            size_t base = ((size_t)(rowbase + 2 * rp) * LX + step) * FF + k;
            us[k * HSTR + rp] = make_float2(x_f[base], x_f[base + (size_t)LX * FF]);
        }
        __syncthreads();   // us ready; hs (prev step) visible

        ull aR[RPAIR], aZ[RPAIR], aGN[RPAIR], aHN[RPAIR];
        {
            ull bR = bcast2(eb.x), bZ = bcast2(eb.y), bGN = bcast2(eb.z), bHN = bcast2(eb.w);
#pragma unroll
            for (int rp = 0; rp < RPAIR; rp++) { aR[rp] = bR; aZ[rp] = bZ; aGN[rp] = bGN; aHN[rp] = bHN; }
        }
        accum_pf(g_encWrz, g_encWn, hsu, HID, t, aR, aZ, aHN);   // hidden part (n -> aHN)
        accum_pf(g_encIrz, g_encIn, usu, FF,  t, aR, aZ, aGN);   // input part  (n -> aGN)
        __syncthreads();   // all reads of hs/us done

        float nh[BT];
#pragma unroll
        for (int rp = 0; rp < RPAIR; rp++) {
            float2 vR = unp2(aR[rp]), vZ = unp2(aZ[rp]), vGN = unp2(aGN[rp]), vHN = unp2(aHN[rp]);
            float r0 = sigf(vR.x), z0 = sigf(vZ.x), n0 = tanhfast(vGN.x + r0 * vHN.x);
            float r1 = sigf(vR.y), z1 = sigf(vZ.y), n1 = tanhfast(vGN.y + r1 * vHN.y);
            float h0 = n0 + z0 * (hreg[2 * rp]     - n0);
            float h1 = n1 + z1 * (hreg[2 * rp + 1] - n1);
            hreg[2 * rp] = h0; hreg[2 * rp + 1] = h1;
            nh[2 * rp] = h0; nh[2 * rp + 1] = h1;
        }
        // four 16B aligned stores (row base t*80)
        *(float4*)(&hs[t * HSTR + 0]) = make_float4(nh[0],  nh[1],  nh[2],  nh[3]);
        *(float4*)(&hs[t * HSTR + 2]) = make_float4(nh[4],  nh[5],  nh[6],  nh[7]);
        *(float4*)(&hs[t * HSTR + 4]) = make_float4(nh[8],  nh[9],  nh[10], nh[11]);
        *(float4*)(&hs[t * HSTR + 6]) = make_float4(nh[12], nh[13], nh[14], nh[15]);
        // next iteration's first __syncthreads orders these writes vs reads
    }

    // ================= decoder =================
    const float4 db = g_decB[t];
    const float  b0 = g_hb0[t];

    for (int i = 0; i < LY; i++) {
        const int j = (i == 0) ? 0 : (i - 1);
        // load dec input: concat(y_t[:, j, 0:22], p[:, j, 0:10]) -> 32 feats
        {
            int k = t & (DECIN - 1), rp = t >> 5;     // 256 threads == DECIN*RPAIR
            int r0 = rowbase + 2 * rp;
            float a, b;
            if (k < FT) {
                size_t base = ((size_t)r0 * (LY + 1) + j) * FT + k;
                a = y_t[base]; b = y_t[base + (size_t)(LY + 1) * FT];
            } else {
                size_t base = ((size_t)r0 * (LY + 1) + j) * FOUTV + (k - FT);
                a = p[base]; b = p[base + (size_t)(LY + 1) * FOUTV];
            }
            us[k * HSTR + rp] = make_float2(a, b);
        }
        __syncthreads();

        ull aR[RPAIR], aZ[RPAIR], aGN[RPAIR], aHN[RPAIR];
        {
            ull bR = bcast2(db.x), bZ = bcast2(db.y), bGN = bcast2(db.z), bHN = bcast2(db.w);
#pragma unroll
            for (int rp = 0; rp < RPAIR; rp++) { aR[rp] = bR; aZ[rp] = bZ; aGN[rp] = bGN; aHN[rp] = bHN; }
        }
        accum_pf(g_decWrz, g_decWn, hsu, HID,   t, aR, aZ, aHN);
        accum_pf(g_decIrz, g_decIn, usu, DECIN, t, aR, aZ, aGN);
        __syncthreads();   // reads of hs done -> safe to overwrite

        float nh[BT];
#pragma unroll
        for (int rp = 0; rp < RPAIR; rp++) {
            float2 vR = unp2(aR[rp]), vZ = unp2(aZ[rp]), vGN = unp2(aGN[rp]), vHN = unp2(aHN[rp]);
            float r0 = sigf(vR.x), z0 = sigf(vZ.x), n0 = tanhfast(vGN.x + r0 * vHN.x);
            float r1 = sigf(vR.y), z1 = sigf(vZ.y), n1 = tanhfast(vGN.y + r1 * vHN.y);
            float h0 = n0 + z0 * (hreg[2 * rp]     - n0);
            float h1 = n1 + z1 * (hreg[2 * rp + 1] - n1);
            hreg[2 * rp] = h0; hreg[2 * rp + 1] = h1;
            nh[2 * rp] = h0; nh[2 * rp + 1] = h1;
        }
        *(float4*)(&hs[t * HSTR + 0]) = make_float4(nh[0],  nh[1],  nh[2],  nh[3]);
        *(float4*)(&hs[t * HSTR + 2]) = make_float4(nh[4],  nh[5],  nh[6],  nh[7]);
        *(float4*)(&hs[t * HSTR + 4]) = make_float4(nh[8],  nh[9],  nh[10], nh[11]);
        *(float4*)(&hs[t * HSTR + 6]) = make_float4(nh[12], nh[13], nh[14], nh[15]);
        __syncthreads();   // new h visible for the head GEMM

        // ---- head layer 0: a = smelu(h2 @ W0^T + b0), 256 combined units ----
        ull aA[RPAIR];
        {
            ull b0p = bcast2(b0);
#pragma unroll
            for (int rp = 0; rp < RPAIR; rp++) aA[rp] = b0p;
        }
        {
            float wA[GRP], wB[GRP], wC[GRP], wD[GRP];
            load_grpH(g_hW0T, t, 0,   wA);
            load_grpH(g_hW0T, t, GRP, wB);
            for (int k0 = 0; k0 < HID; k0 += 4 * GRP) {
                load_grpH(g_hW0T, t, k0 + 2 * GRP, wC);
                load_grpH(g_hW0T, t, k0 + 3 * GRP, wD);
                consume_grpH(wA, hsu, k0,       aA);
                consume_grpH(wB, hsu, k0 + GRP, aA);
                load_grpH(g_hW0T, t, k0 + 4 * GRP, wA);  // pad-covered on last iter
                load_grpH(g_hW0T, t, k0 + 5 * GRP, wB);  // pad-covered on last iter
                consume_grpH(wC, hsu, k0 + 2 * GRP, aA);
                consume_grpH(wD, hsu, k0 + 3 * GRP, aA);
            }
        }
#pragma unroll
        for (int rp = 0; rp < RPAIR; rp++) {
            float2 v = unp2(aA[rp]);
            aps[t * HSTR + rp] = make_float2(smelu(v.x), smelu(v.y));
        }
        __syncthreads();   // aps ready

        // ---- head layer 1: 10 outputs x 16 rows = 160 dots of length 128 ----
        if (t < BT * FOUTV) {
            int row = t / FOUTV, o = t - row * FOUTV;
            int koff = (o < 2) ? 0 : REGH;
            const float* apf = (const float*)aps;   // flat: unit k -> k*2*HSTR + row
            const float* w   = &g_hW1[o * REGH];
            float s = g_hb1[o];
#pragma unroll 8
            for (int k = 0; k < REGH; k++)
                s += apf[(koff + k) * (2 * HSTR) + row] * w[k];
            out[((size_t)(rowbase + row) * LY + i) * FOUTV + o] = s;
        }
        // next iteration's first __syncthreads fences aps/us reuse
    }
}

// ---------------------------------------------------------------------------
// Launch. d_in order: x_f, x(unused), y_t, p, enc_Wih, enc_Whh, enc_bih,
// enc_bhh, dec_Wih, dec_Whh, dec_bih, dec_bhh, th_W0, th_b0, th_W1, th_b1,
// cl_W0, cl_b0, cl_W1, cl_b1
// ---------------------------------------------------------------------------
extern "C" void kernel_launch(void* const* d_in, const int* in_sizes, int n_in,
                              void* d_out, int out_size)
{
    const float* x_f    = (const float*)d_in[0];
    const float* y_t    = (const float*)d_in[2];
    const float* p      = (const float*)d_in[3];
    const float* encWih = (const float*)d_in[4];
    const float* encWhh = (const float*)d_in[5];
    const float* encBih = (const float*)d_in[6];
    const float* encBhh = (const float*)d_in[7];
    const float* decWih = (const float*)d_in[8];
    const float* decWhh = (const float*)d_in[9];
    const float* decBih = (const float*)d_in[10];
    const float* decBhh = (const float*)d_in[11];
    const float* thW0   = (const float*)d_in[12];
    const float* thB0   = (const float*)d_in[13];
    const float* thW1   = (const float*)d_in[14];
    const float* thB1   = (const float*)d_in[15];
    const float* clW0   = (const float*)d_in[16];
    const float* clB0   = (const float*)d_in[17];
    const float* clW1   = (const float*)d_in[18];
    const float* clB1   = (const float*)d_in[19];
    float* out = (float*)d_out;

    setup_kernel<<<256, 256>>>(encWih, encWhh, encBih, encBhh,
                               decWih, decWhh, decBih, decBhh,
                               thW0, thB0, thW1, thB1,
                               clW0, clB0, clW1, clB1);
    rnn_kernel<<<NCTA, NTHR>>>(x_f, y_t, p, out);
}

// round 17
// speedup vs baseline: 1.4045x; 1.0272x over previous
#include <cuda_runtime.h>
#include <cuda_bf16.h>
#include <cstddef>

// ---------------------------------------------------------------------------
// Problem constants
// ---------------------------------------------------------------------------
#define NB     2048     // batch
#define LX     168      // encoder steps
#define FF     64       // encoder features
#define HID    256      // hidden
#define LY     72       // decoder steps
#define FT     22       // future feats
#define FOUTV  10       // output size
#define DECIN  32       // FT + FOUTV
#define REGH   128
#define CLSH   128

#define BT     16       // batch rows per CTA
#define NCTA   (NB / BT)        // 128
#define NTHR   256
#define RPAIR  8        // row pairs per CTA (= per thread)
#define HSTR   10       // float2 stride per k-row (80B: 16B-aligned)
#define GRP    4        // weight prefetch group
#define KPAD   8        // pad rows: distance-2 weight pipeline over-reads K..K+7

// ---------------------------------------------------------------------------
// Packed weight scratch (device globals -- no allocation allowed).
//   W*rz[k][u] = (wr, wz)  -> one LDG.64 ;  W*n[k][u] = wn -> one LDG.32
// ---------------------------------------------------------------------------
__device__ float2 g_encWrz[(HID + KPAD) * HID];
__device__ float  g_encWn [(HID + KPAD) * HID];
__device__ float2 g_encIrz[(FF + KPAD) * HID];
__device__ float  g_encIn [(FF + KPAD) * HID];
__device__ float2 g_decWrz[(HID + KPAD) * HID];
__device__ float  g_decWn [(HID + KPAD) * HID];
__device__ float2 g_decIrz[(DECIN + KPAD) * HID];
__device__ float  g_decIn [(DECIN + KPAD) * HID];
__device__ float  g_hW0T[(HID + KPAD) * 256]; // head L0: 0..127 temphr, 128..255 class
__device__ float  g_hb0 [256];
__device__ float  g_hW1 [FOUTV * REGH];       // rows 0..1 temphr, 2..9 class
__device__ float  g_hb1 [FOUTV];
__device__ float4 g_encB[HID];                // (bir+bhr, biz+bhz, bin, bhn)
__device__ float4 g_decB[HID];

// ---------------------------------------------------------------------------
// f32x2 packed-FMA helpers (sm_103a: fma.rn.f32x2)
// ---------------------------------------------------------------------------
typedef unsigned long long ull;

__device__ __forceinline__ ull fma2(ull a, ull b, ull c) {
    ull d;
    asm("fma.rn.f32x2 %0, %1, %2, %3;" : "=l"(d) : "l"(a), "l"(b), "l"(c));
    return d;
}
__device__ __forceinline__ ull bcast2(float x) {
    ull d; unsigned int xi = __float_as_uint(x);
    asm("mov.b64 %0, {%1, %2};" : "=l"(d) : "r"(xi), "r"(xi));
    return d;
}
__device__ __forceinline__ float2 unp2(ull v) {
    unsigned int lo, hi;
    asm("mov.b64 {%0, %1}, %2;" : "=r"(lo), "=r"(hi) : "l"(v));
    return make_float2(__uint_as_float(lo), __uint_as_float(hi));
}

__device__ __forceinline__ float sigf(float x) {
    return __fdividef(1.0f, 1.0f + __expf(-x));
}
__device__ __forceinline__ float tanhfast(float x) {
    return __fdividef(2.0f, 1.0f + __expf(-2.0f * x)) - 1.0f;
}
__device__ __forceinline__ float smelu(float x) {
    if (x >= 1.1f) return x;
    if (x <= -1.1f) return 0.0f;
    float u = x + 1.1f;
    return u * u * (1.0f / 4.4f);
}

// ---------------------------------------------------------------------------
// Setup kernel: transpose/pack weights into streaming-friendly layouts.
// ---------------------------------------------------------------------------
__global__ void setup_kernel(
    const float* __restrict__ encWih, const float* __restrict__ encWhh,
    const float* __restrict__ encBih, const float* __restrict__ encBhh,
    const float* __restrict__ decWih, const float* __restrict__ decWhh,
    const float* __restrict__ decBih, const float* __restrict__ decBhh,
    const float* __restrict__ thW0,  const float* __restrict__ thB0,
    const float* __restrict__ thW1,  const float* __restrict__ thB1,
    const float* __restrict__ clW0,  const float* __restrict__ clB0,
    const float* __restrict__ clW1,  const float* __restrict__ clB1)
{
    int id = blockIdx.x * blockDim.x + threadIdx.x;   // 0 .. 65535
    int u  = id & 255;
    int k  = id >> 8;                                  // 0 .. 255

    g_encWrz[k * HID + u] = make_float2(encWhh[u * HID + k], encWhh[(HID + u) * HID + k]);
    g_encWn [k * HID + u] = encWhh[(2 * HID + u) * HID + k];
    g_decWrz[k * HID + u] = make_float2(decWhh[u * HID + k], decWhh[(HID + u) * HID + k]);
    g_decWn [k * HID + u] = decWhh[(2 * HID + u) * HID + k];

    g_hW0T[k * 256 + u] = (u < REGH) ? thW0[u * HID + k] : clW0[(u - REGH) * HID + k];

    if (k < FF) {
        g_encIrz[k * HID + u] = make_float2(encWih[u * FF + k], encWih[(HID + u) * FF + k]);
        g_encIn [k * HID + u] = encWih[(2 * HID + u) * FF + k];
    }
    if (k < DECIN) {
        g_decIrz[k * HID + u] = make_float2(decWih[u * DECIN + k], decWih[(HID + u) * DECIN + k]);
        g_decIn [k * HID + u] = decWih[(2 * HID + u) * DECIN + k];
    }
    if (id < HID) {
        g_encB[id] = make_float4(encBih[id] + encBhh[id],
                                 encBih[HID + id] + encBhh[HID + id],
                                 encBih[2 * HID + id],
                                 encBhh[2 * HID + id]);
        g_decB[id] = make_float4(decBih[id] + decBhh[id],
                                 decBih[HID + id] + decBhh[HID + id],
                                 decBih[2 * HID + id],
                                 decBhh[2 * HID + id]);
        g_hb0[id] = (id < REGH) ? thB0[id] : clB0[id - REGH];
    }
    if (id < FOUTV * REGH) {
        int o = id >> 7, kk = id & 127;
        g_hW1[id] = (o < 2) ? thW1[o * REGH + kk] : clW1[(o - 2) * CLSH + kk];
    }
    if (id < FOUTV) g_hb1[id] = (id < 2) ? thB1[id] : clB1[id - 2];
}

// ---------------------------------------------------------------------------
// Activation row buffer (8 row-pairs = 4x LDS.128), double-buffered.
// ---------------------------------------------------------------------------
struct ActRow { ulonglong2 p0, p1, p2, p3; };

__device__ __forceinline__ void ld_act(ActRow& a, const ull* __restrict__ src, int k) {
    const ull* s = src + k * HSTR;
    a.p0 = *(const ulonglong2*)(s + 0);
    a.p1 = *(const ulonglong2*)(s + 2);
    a.p2 = *(const ulonglong2*)(s + 4);
    a.p3 = *(const ulonglong2*)(s + 6);
}

__device__ __forceinline__ void fma_row(
    const ActRow& a, float2 wrz, float wn,
    ull aR[RPAIR], ull aZ[RPAIR], ull aN[RPAIR])
{
    ull br = bcast2(wrz.x), bz = bcast2(wrz.y), bn = bcast2(wn);
    aR[0] = fma2(a.p0.x, br, aR[0]); aZ[0] = fma2(a.p0.x, bz, aZ[0]); aN[0] = fma2(a.p0.x, bn, aN[0]);
    aR[1] = fma2(a.p0.y, br, aR[1]); aZ[1] = fma2(a.p0.y, bz, aZ[1]); aN[1] = fma2(a.p0.y, bn, aN[1]);
    aR[2] = fma2(a.p1.x, br, aR[2]); aZ[2] = fma2(a.p1.x, bz, aZ[2]); aN[2] = fma2(a.p1.x, bn, aN[2]);
    aR[3] = fma2(a.p1.y, br, aR[3]); aZ[3] = fma2(a.p1.y, bz, aZ[3]); aN[3] = fma2(a.p1.y, bn, aN[3]);
    aR[4] = fma2(a.p2.x, br, aR[4]); aZ[4] = fma2(a.p2.x, bz, aZ[4]); aN[4] = fma2(a.p2.x, bn, aN[4]);
    aR[5] = fma2(a.p2.y, br, aR[5]); aZ[5] = fma2(a.p2.y, bz, aZ[5]); aN[5] = fma2(a.p2.y, bn, aN[5]);
    aR[6] = fma2(a.p3.x, br, aR[6]); aZ[6] = fma2(a.p3.x, bz, aZ[6]); aN[6] = fma2(a.p3.x, bn, aN[6]);
    aR[7] = fma2(a.p3.y, br, aR[7]); aZ[7] = fma2(a.p3.y, bz, aZ[7]); aN[7] = fma2(a.p3.y, bn, aN[7]);
}

__device__ __forceinline__ void fma_rowH(
    const ActRow& a, float w, ull aA[RPAIR])
{
    ull bw = bcast2(w);
    aA[0] = fma2(a.p0.x, bw, aA[0]); aA[1] = fma2(a.p0.y, bw, aA[1]);
    aA[2] = fma2(a.p1.x, bw, aA[2]); aA[3] = fma2(a.p1.y, bw, aA[3]);
    aA[4] = fma2(a.p2.x, bw, aA[4]); aA[5] = fma2(a.p2.y, bw, aA[5]);
    aA[6] = fma2(a.p3.x, bw, aA[6]); aA[7] = fma2(a.p3.y, bw, aA[7]);
}

// ---------------------------------------------------------------------------
// Software-pipelined GEMM pieces: weights distance-2 prefetch (registers),
// activations distance-1 double-buffer (prefetch k+1's LDS before k's FMAs).
// ---------------------------------------------------------------------------
__device__ __forceinline__ void load_grpW(
    const float2* __restrict__ Wrz, const float* __restrict__ Wn,
    int u, int k0, float2 wrz[GRP], float wn[GRP])
{
#pragma unroll
    for (int j = 0; j < GRP; j++) {
        wrz[j] = Wrz[(k0 + j) * HID + u];
        wn [j] = Wn [(k0 + j) * HID + u];
    }
}

// Process rows k0..k0+3. On entry qa holds row k0's acts; on exit qa holds
// row k0+4's acts (the final prefetch reads row k0+4 -- callers guarantee the
// activation array has K+1 rows, so the tail over-read stays in bounds).
__device__ __forceinline__ void consume_grpW2(
    const float2 wrz[GRP], const float wn[GRP],
    const ull* __restrict__ src, int k0, ActRow& qa, ActRow& qb,
    ull aR[RPAIR], ull aZ[RPAIR], ull aN[RPAIR])
{
    ld_act(qb, src, k0 + 1); fma_row(qa, wrz[0], wn[0], aR, aZ, aN);
    ld_act(qa, src, k0 + 2); fma_row(qb, wrz[1], wn[1], aR, aZ, aN);
    ld_act(qb, src, k0 + 3); fma_row(qa, wrz[2], wn[2], aR, aZ, aN);
    ld_act(qa, src, k0 + 4); fma_row(qb, wrz[3], wn[3], aR, aZ, aN);
}

// Distance-2 weight pipeline over K rows (K multiple of 4*GRP: 256/64/32 ok).
// Weight tail over-reads rows K..K+2*GRP-1 (KPAD-covered). Act tail over-reads
// row K (activation arrays declare K+1 rows).
__device__ __forceinline__ void accum_pf(
    const float2* __restrict__ Wrz, const float* __restrict__ Wn,
    const ull* __restrict__ src, int K, int u,
    ull aR[RPAIR], ull aZ[RPAIR], ull aN[RPAIR])
{
    float2 wA[GRP], wB[GRP], wC[GRP], wD[GRP];
    float  nA[GRP], nB[GRP], nC[GRP], nD[GRP];
    ActRow qa, qb;
    load_grpW(Wrz, Wn, u, 0,   wA, nA);
    load_grpW(Wrz, Wn, u, GRP, wB, nB);
    ld_act(qa, src, 0);
    for (int k0 = 0; k0 < K; k0 += 4 * GRP) {
        load_grpW(Wrz, Wn, u, k0 + 2 * GRP, wC, nC);
        load_grpW(Wrz, Wn, u, k0 + 3 * GRP, wD, nD);
        consume_grpW2(wA, nA, src, k0,           qa, qb, aR, aZ, aN);
        consume_grpW2(wB, nB, src, k0 + GRP,     qa, qb, aR, aZ, aN);
        load_grpW(Wrz, Wn, u, k0 + 4 * GRP, wA, nA);   // pad-covered on last iter
        load_grpW(Wrz, Wn, u, k0 + 5 * GRP, wB, nB);   // pad-covered on last iter
        consume_grpW2(wC, nC, src, k0 + 2 * GRP, qa, qb, aR, aZ, aN);
        consume_grpW2(wD, nD, src, k0 + 3 * GRP, qa, qb, aR, aZ, aN);
    }
}

// Head layer-0 variants (one scalar weight per k).
__device__ __forceinline__ void load_grpH(
    const float* __restrict__ W, int u, int k0, float w[GRP])
{
#pragma unroll
    for (int j = 0; j < GRP; j++) w[j] = W[(k0 + j) * 256 + u];
}
__device__ __forceinline__ void consume_grpH2(
    const float w[GRP], const ull* __restrict__ src, int k0,
    ActRow& qa, ActRow& qb, ull aA[RPAIR])
{
    ld_act(qb, src, k0 + 1); fma_rowH(qa, w[0], aA);
    ld_act(qa, src, k0 + 2); fma_rowH(qb, w[1], aA);
    ld_act(qb, src, k0 + 3); fma_rowH(qa, w[2], aA);
    ld_act(qa, src, k0 + 4); fma_rowH(qb, w[3], aA);
}

// ---------------------------------------------------------------------------
// Persistent recurrent kernel: one CTA per 16 batch rows, full time loop.
// Thread t owns hidden/head unit t and all 8 row-pairs.
// ---------------------------------------------------------------------------
__global__ void __launch_bounds__(NTHR, 1) rnn_kernel(
    const float* __restrict__ x_f,   // (N, LX, FF)
    const float* __restrict__ y_t,   // (N, LY+1, FT)
    const float* __restrict__ p,     // (N, LY+1, FOUTV)
    float* __restrict__ out)         // (N, LY, FOUTV)
{
    __shared__ float2 hs [(HID + 1) * HSTR]; // hidden state (+1 row: act over-read)
    __shared__ float2 us [(FF + 1)  * HSTR]; // step input   (+1 row: act over-read)
    __shared__ float2 aps[256 * HSTR];       // head-0 activations, packed

    const int t       = threadIdx.x;     // unit index
    const int rowbase = blockIdx.x * BT;

    float hreg[BT];
#pragma unroll
    for (int r = 0; r < BT; r++) hreg[r] = 0.0f;
#pragma unroll
    for (int rp = 0; rp < RPAIR; rp++) hs[t * HSTR + rp] = make_float2(0.0f, 0.0f);
    if (t < HSTR) {  // zero the over-read pad rows (never consumed, but keep defined)
        hs[HID * HSTR + t] = make_float2(0.0f, 0.0f);
        us[FF  * HSTR + t] = make_float2(0.0f, 0.0f);
    }

    const ull* hsu = (const ull*)hs;
    const ull* usu = (const ull*)us;

    const float4 eb = g_encB[t];

    // ================= encoder =================
    for (int step = 0; step < LX; step++) {
        // load u tile: x_f[rowbase.., step, :] packed into us[k][rp]
        for (int idx = t; idx < FF * RPAIR; idx += NTHR) {
            int k = idx & (FF - 1), rp = idx >> 6;
            size_t base = ((size_t)(rowbase + 2 * rp) * LX + step) * FF + k;
            us[k * HSTR + rp] = make_float2(x_f[base], x_f[base + (size_t)LX * FF]);
        }
        __syncthreads();   // us ready; hs (prev step) visible

        ull aR[RPAIR], aZ[RPAIR], aGN[RPAIR], aHN[RPAIR];
        {
            ull bR = bcast2(eb.x), bZ = bcast2(eb.y), bGN = bcast2(eb.z), bHN = bcast2(eb.w);
#pragma unroll
            for (int rp = 0; rp < RPAIR; rp++) { aR[rp] = bR; aZ[rp] = bZ; aGN[rp] = bGN; aHN[rp] = bHN; }
        }
        accum_pf(g_encWrz, g_encWn, hsu, HID, t, aR, aZ, aHN);   // hidden part (n -> aHN)
        accum_pf(g_encIrz, g_encIn, usu, FF,  t, aR, aZ, aGN);   // input part  (n -> aGN)
        __syncthreads();   // all reads of hs/us done

        float nh[BT];
#pragma unroll
        for (int rp = 0; rp < RPAIR; rp++) {
            float2 vR = unp2(aR[rp]), vZ = unp2(aZ[rp]), vGN = unp2(aGN[rp]), vHN = unp2(aHN[rp]);
            float r0 = sigf(vR.x), z0 = sigf(vZ.x), n0 = tanhfast(vGN.x + r0 * vHN.x);
            float r1 = sigf(vR.y), z1 = sigf(vZ.y), n1 = tanhfast(vGN.y + r1 * vHN.y);
            float h0 = n0 + z0 * (hreg[2 * rp]     - n0);
            float h1 = n1 + z1 * (hreg[2 * rp + 1] - n1);
            hreg[2 * rp] = h0; hreg[2 * rp + 1] = h1;
            nh[2 * rp] = h0; nh[2 * rp + 1] = h1;
        }
        // four 16B aligned stores (row base t*80)
        *(float4*)(&hs[t * HSTR + 0]) = make_float4(nh[0],  nh[1],  nh[2],  nh[3]);
        *(float4*)(&hs[t * HSTR + 2]) = make_float4(nh[4],  nh[5],  nh[6],  nh[7]);
        *(float4*)(&hs[t * HSTR + 4]) = make_float4(nh[8],  nh[9],  nh[10], nh[11]);
        *(float4*)(&hs[t * HSTR + 6]) = make_float4(nh[12], nh[13], nh[14], nh[15]);
        // next iteration's first __syncthreads orders these writes vs reads
    }

    // ================= decoder =================
    const float4 db = g_decB[t];
    const float  b0 = g_hb0[t];

    for (int i = 0; i < LY; i++) {
        const int j = (i == 0) ? 0 : (i - 1);
        // load dec input: concat(y_t[:, j, 0:22], p[:, j, 0:10]) -> 32 feats
        {
            int k = t & (DECIN - 1), rp = t >> 5;     // 256 threads == DECIN*RPAIR
            int r0 = rowbase + 2 * rp;
            float a, b;
            if (k < FT) {
                size_t base = ((size_t)r0 * (LY + 1) + j) * FT + k;
                a = y_t[base]; b = y_t[base + (size_t)(LY + 1) * FT];
            } else {
                size_t base = ((size_t)r0 * (LY + 1) + j) * FOUTV + (k - FT);
                a = p[base]; b = p[base + (size_t)(LY + 1) * FOUTV];
            }
            us[k * HSTR + rp] = make_float2(a, b);
        }
        __syncthreads();

        ull aR[RPAIR], aZ[RPAIR], aGN[RPAIR], aHN[RPAIR];
        {
            ull bR = bcast2(db.x), bZ = bcast2(db.y), bGN = bcast2(db.z), bHN = bcast2(db.w);
#pragma unroll
            for (int rp = 0; rp < RPAIR; rp++) { aR[rp] = bR; aZ[rp] = bZ; aGN[rp] = bGN; aHN[rp] = bHN; }
        }
        accum_pf(g_decWrz, g_decWn, hsu, HID,   t, aR, aZ, aHN);
        accum_pf(g_decIrz, g_decIn, usu, DECIN, t, aR, aZ, aGN);
        __syncthreads();   // reads of hs done -> safe to overwrite

        float nh[BT];
#pragma unroll
        for (int rp = 0; rp < RPAIR; rp++) {
            float2 vR = unp2(aR[rp]), vZ = unp2(aZ[rp]), vGN = unp2(aGN[rp]), vHN = unp2(aHN[rp]);
            float r0 = sigf(vR.x), z0 = sigf(vZ.x), n0 = tanhfast(vGN.x + r0 * vHN.x);
            float r1 = sigf(vR.y), z1 = sigf(vZ.y), n1 = tanhfast(vGN.y + r1 * vHN.y);
            float h0 = n0 + z0 * (hreg[2 * rp]     - n0);
            float h1 = n1 + z1 * (hreg[2 * rp + 1] - n1);
            hreg[2 * rp] = h0; hreg[2 * rp + 1] = h1;
            nh[2 * rp] = h0; nh[2 * rp + 1] = h1;
        }
        *(float4*)(&hs[t * HSTR + 0]) = make_float4(nh[0],  nh[1],  nh[2],  nh[3]);
        *(float4*)(&hs[t * HSTR + 2]) = make_float4(nh[4],  nh[5],  nh[6],  nh[7]);
        *(float4*)(&hs[t * HSTR + 4]) = make_float4(nh[8],  nh[9],  nh[10], nh[11]);
        *(float4*)(&hs[t * HSTR + 6]) = make_float4(nh[12], nh[13], nh[14], nh[15]);
        __syncthreads();   // new h visible for the head GEMM

        // ---- head layer 0: a = smelu(h2 @ W0^T + b0), 256 combined units ----
        ull aA[RPAIR];
        {
            ull b0p = bcast2(b0);
#pragma unroll
            for (int rp = 0; rp < RPAIR; rp++) aA[rp] = b0p;
        }
        {
            float wA[GRP], wB[GRP], wC[GRP], wD[GRP];
            ActRow qa, qb;
            load_grpH(g_hW0T, t, 0,   wA);
            load_grpH(g_hW0T, t, GRP, wB);
            ld_act(qa, hsu, 0);
            for (int k0 = 0; k0 < HID; k0 += 4 * GRP) {
                load_grpH(g_hW0T, t, k0 + 2 * GRP, wC);
                load_grpH(g_hW0T, t, k0 + 3 * GRP, wD);
                consume_grpH2(wA, hsu, k0,           qa, qb, aA);
                consume_grpH2(wB, hsu, k0 + GRP,     qa, qb, aA);
                load_grpH(g_hW0T, t, k0 + 4 * GRP, wA);  // pad-covered on last iter
                load_grpH(g_hW0T, t, k0 + 5 * GRP, wB);  // pad-covered on last iter
                consume_grpH2(wC, hsu, k0 + 2 * GRP, qa, qb, aA);
                consume_grpH2(wD, hsu, k0 + 3 * GRP, qa, qb, aA);
            }
        }
#pragma unroll
        for (int rp = 0; rp < RPAIR; rp++) {
            float2 v = unp2(aA[rp]);
            aps[t * HSTR + rp] = make_float2(smelu(v.x), smelu(v.y));
        }
        __syncthreads();   // aps ready

        // ---- head layer 1: 10 outputs x 16 rows = 160 dots of length 128 ----
        if (t < BT * FOUTV) {
            int row = t / FOUTV, o = t - row * FOUTV;
            int koff = (o < 2) ? 0 : REGH;
            const float* apf = (const float*)aps;   // flat: unit k -> k*2*HSTR + row
            const float* w   = &g_hW1[o * REGH];
            float s = g_hb1[o];
#pragma unroll 8
            for (int k = 0; k < REGH; k++)
                s += apf[(koff + k) * (2 * HSTR) + row] * w[k];
            out[((size_t)(rowbase + row) * LY + i) * FOUTV + o] = s;
        }
        // next iteration's first __syncthreads fences aps/us reuse
    }
}

// ---------------------------------------------------------------------------
// Launch. d_in order: x_f, x(unused), y_t, p, enc_Wih, enc_Whh, enc_bih,
// enc_bhh, dec_Wih, dec_Whh, dec_bih, dec_bhh, th_W0, th_b0, th_W1, th_b1,
// cl_W0, cl_b0, cl_W1, cl_b1
// ---------------------------------------------------------------------------
extern "C" void kernel_launch(void* const* d_in, const int* in_sizes, int n_in,
                              void* d_out, int out_size)
{
    const float* x_f    = (const float*)d_in[0];
    const float* y_t    = (const float*)d_in[2];
    const float* p      = (const float*)d_in[3];
    const float* encWih = (const float*)d_in[4];
    const float* encWhh = (const float*)d_in[5];
    const float* encBih = (const float*)d_in[6];
    const float* encBhh = (const float*)d_in[7];
    const float* decWih = (const float*)d_in[8];
    const float* decWhh = (const float*)d_in[9];
    const float* decBih = (const float*)d_in[10];
    const float* decBhh = (const float*)d_in[11];
    const float* thW0   = (const float*)d_in[12];
    const float* thB0   = (const float*)d_in[13];
    const float* thW1   = (const float*)d_in[14];
    const float* thB1   = (const float*)d_in[15];
    const float* clW0   = (const float*)d_in[16];
    const float* clB0   = (const float*)d_in[17];
    const float* clW1   = (const float*)d_in[18];
    const float* clB1   = (const float*)d_in[19];
    float* out = (float*)d_out;

    setup_kernel<<<256, 256>>>(encWih, encWhh, encBih, encBhh,
                               decWih, decWhh, decBih, decBhh,
                               thW0, thB0, thW1, thB1,
                               clW0, clB0, clW1, clB1);
    rnn_kernel<<<NCTA, NTHR>>>(x_f, y_t, p, out);
}